// round 6
// baseline (speedup 1.0000x reference)
#include <cuda_runtime.h>
#include <cuda_bf16.h>
#include <cstdint>

// LSTM: B=4096, T=2048, I=1, H=8, then FC [H]->[4].
// R6: 16 lanes/batch-group, TWO independent batch chains per group
// (register-interleaved) -> 1024 warps x 2 chains. Weights shared between
// chains (same lane role). Per group: lower 8 lanes own gates (i,g), upper 8
// own (f,o) + (c,h). h broadcast via double-buffered smem (2 STS + 1 BAR +
// 4 LDS.128 per warp-step covering 4 batches). Gate dots use packed
// fma.rn.f32x2 (FFMA2): h pairs arrive packed from LDS.128, weights
// pre-packed. Activations via MUFU.TANH, sigmoid prescale folded in.

#define B_TOTAL 4096
#define T_STEPS 2048
#define NT4     (T_STEPS / 4)

__device__ __forceinline__ float tanhf_mufu(float x) {
    float r; asm("tanh.approx.f32 %0, %1;" : "=f"(r) : "f"(x)); return r;
}
__device__ __forceinline__ uint64_t packf2(float lo, float hi) {
    uint64_t r; asm("mov.b64 %0, {%1, %2};" : "=l"(r) : "f"(lo), "f"(hi)); return r;
}
__device__ __forceinline__ void unpackf2(uint64_t p, float& lo, float& hi) {
    asm("mov.b64 {%0, %1}, %2;" : "=f"(lo), "=f"(hi) : "l"(p));
}
__device__ __forceinline__ uint64_t ffma2(uint64_t a, uint64_t b, uint64_t c) {
    uint64_t d; asm("fma.rn.f32x2 %0, %1, %2, %3;" : "=l"(d) : "l"(a), "l"(b), "l"(c)); return d;
}

__global__ __launch_bounds__(32)
void lstm_fused_kernel(const float* __restrict__ x,
                       const float* __restrict__ w_ih,
                       const float* __restrict__ w_hh,
                       const float* __restrict__ b_ih,
                       const float* __restrict__ b_hh,
                       const float* __restrict__ w_fc,
                       const float* __restrict__ b_fc,
                       float* __restrict__ out)
{
    // [parity][grp][chain][unit] ; rows are 32B-aligned for LDS.128.
    __shared__ float hbuf[2][2][2][8];

    const int lane = threadIdx.x & 31;
    const int grp  = lane >> 4;        // 16-lane group within warp
    const int l    = lane & 15;
    const int u    = l & 7;
    const bool hi  = (l >= 8);         // upper half owns (f,o) and (c,h)

    const int G  = blockIdx.x * 2 + grp;   // global group id (0..2047)
    const int b0 = 2 * G;                  // chain-a batch
    const int b1 = 2 * G + 1;              // chain-b batch

    // PyTorch gate rows: i=[0,8), f=[8,16), g=[16,24), o=[24,32).
    // Gate A: lower->i, upper->f (sigmoid, prescale 0.5).
    // Gate B: lower->g (tanh, scale 1), upper->o (sigmoid, prescale 0.5).
    const int   rowA = hi ? (8 + u)  : u;
    const int   rowB = hi ? (24 + u) : (16 + u);
    const float sA   = 0.5f;
    const float sB   = hi ? 0.5f : 1.0f;
    const float alB  = hi ? 0.5f : 1.0f;
    const float beB  = hi ? 0.5f : 0.0f;

    // Packed weight pairs: wpX[j] = (w[2j], w[2j+1]) prescaled.
    uint64_t wpA[4], wpB[4];
    float wxA, wxB, bbA, bbB;
    {
        wxA = sA * w_ih[rowA];
        wxB = sB * w_ih[rowB];
        bbA = sA * (b_ih[rowA] + b_hh[rowA]);
        bbB = sB * (b_ih[rowB] + b_hh[rowB]);
#pragma unroll
        for (int j = 0; j < 4; j++) {
            wpA[j] = packf2(sA * w_hh[rowA * 8 + 2 * j], sA * w_hh[rowA * 8 + 2 * j + 1]);
            wpB[j] = packf2(sB * w_hh[rowB * 8 + 2 * j], sB * w_hh[rowB * 8 + 2 * j + 1]);
        }
    }

    float ha = 0.0f, ca = 0.0f;   // chain a state (valid in upper half)
    float hb = 0.0f, cb = 0.0f;   // chain b state

    const float4* xba = reinterpret_cast<const float4*>(x + (size_t)b0 * T_STEPS);
    const float4* xbb = reinterpret_cast<const float4*>(x + (size_t)b1 * T_STEPS);
    float4 xva = xba[0];
    float4 xvb = xbb[0];

    for (int t4 = 0; t4 < NT4; t4++) {
        const int nx = (t4 + 1 < NT4) ? (t4 + 1) : t4;   // branchless prefetch
        const float4 xna = xba[nx];
        const float4 xnb = xbb[nx];

        const float xsa[4] = { xva.x, xva.y, xva.z, xva.w };
        const float xsb[4] = { xvb.x, xvb.y, xvb.z, xvb.w };
#pragma unroll
        for (int k = 0; k < 4; k++) {
            const int p = k & 1;           // smem double-buffer parity

            if (hi) {
                hbuf[p][grp][0][u] = ha;   // publish both chains' h
                hbuf[p][grp][1][u] = hb;
            }
            __syncthreads();               // 1-warp block: cheap BAR + fence

            // Packed h pairs: qa0 = {(h0,h1),(h2,h3)}, qa1 = {(h4,h5),(h6,h7)}
            const ulonglong2* hva = reinterpret_cast<const ulonglong2*>(&hbuf[p][grp][0][0]);
            const ulonglong2* hvb = reinterpret_cast<const ulonglong2*>(&hbuf[p][grp][1][0]);
            const ulonglong2 qa0 = hva[0], qa1 = hva[1];
            const ulonglong2 qb0 = hvb[0], qb1 = hvb[1];

            // ---- chain a ----
            {
                const float xt = xsa[k];
                uint64_t accA = packf2(bbA, xt * wxA);
                uint64_t accB = packf2(bbB, xt * wxB);
                accA = ffma2(qa0.x, wpA[0], accA);  accB = ffma2(qa0.x, wpB[0], accB);
                accA = ffma2(qa0.y, wpA[1], accA);  accB = ffma2(qa0.y, wpB[1], accB);
                accA = ffma2(qa1.x, wpA[2], accA);  accB = ffma2(qa1.x, wpB[2], accB);
                accA = ffma2(qa1.y, wpA[3], accA);  accB = ffma2(qa1.y, wpB[3], accB);
                float aAl, aAh, aBl, aBh;
                unpackf2(accA, aAl, aAh);
                unpackf2(accB, aBl, aBh);
                const float aA = aAl + aAh;
                const float aB = aBl + aBh;

                const float tA = tanhf_mufu(aA);
                const float tB = tanhf_mufu(aB);
                const float rA = fmaf(0.5f, tA, 0.5f);   // i (lo) / f (hi)
                const float gB = fmaf(alB,  tB, beB);    // g (lo) / o (hi)

                const float m   = rA * gB;               // i*g (lower valid)
                const float m_u = __shfl_xor_sync(0xffffffffu, m, 8, 16);

                ca = fmaf(rA, ca, m_u);                  // f*c + i*g (upper)
                const float tc = tanhf_mufu(ca);
                ha = gB * tc;                            // o * tanh(c) (upper)
            }
            // ---- chain b ----
            {
                const float xt = xsb[k];
                uint64_t accA = packf2(bbA, xt * wxA);
                uint64_t accB = packf2(bbB, xt * wxB);
                accA = ffma2(qb0.x, wpA[0], accA);  accB = ffma2(qb0.x, wpB[0], accB);
                accA = ffma2(qb0.y, wpA[1], accA);  accB = ffma2(qb0.y, wpB[1], accB);
                accA = ffma2(qb1.x, wpA[2], accA);  accB = ffma2(qb1.x, wpB[2], accB);
                accA = ffma2(qb1.y, wpA[3], accA);  accB = ffma2(qb1.y, wpB[3], accB);
                float aAl, aAh, aBl, aBh;
                unpackf2(accA, aAl, aAh);
                unpackf2(accB, aBl, aBh);
                const float aA = aAl + aAh;
                const float aB = aBl + aBh;

                const float tA = tanhf_mufu(aA);
                const float tB = tanhf_mufu(aB);
                const float rA = fmaf(0.5f, tA, 0.5f);
                const float gB = fmaf(alB,  tB, beB);

                const float m   = rA * gB;
                const float m_u = __shfl_xor_sync(0xffffffffu, m, 8, 16);

                cb = fmaf(rA, cb, m_u);
                const float tc = tanhf_mufu(cb);
                hb = gB * tc;
            }
        }
        xva = xna;
        xvb = xnb;
    }

    // FC head for both chains: out[b][kk] = b_fc[kk] + sum_u h_u w_fc[kk*8+u]
    // h valid in upper 8 lanes; width-8 xor reduction stays in that segment.
#pragma unroll
    for (int ch = 0; ch < 2; ch++) {
        const float hv = (ch == 0) ? ha : hb;
        const int   bb = (ch == 0) ? b0 : b1;
        float p0 = hv * w_fc[0 * 8 + u];
        float p1 = hv * w_fc[1 * 8 + u];
        float p2 = hv * w_fc[2 * 8 + u];
        float p3 = hv * w_fc[3 * 8 + u];
#pragma unroll
        for (int off = 4; off >= 1; off >>= 1) {
            p0 += __shfl_xor_sync(0xffffffffu, p0, off, 8);
            p1 += __shfl_xor_sync(0xffffffffu, p1, off, 8);
            p2 += __shfl_xor_sync(0xffffffffu, p2, off, 8);
            p3 += __shfl_xor_sync(0xffffffffu, p3, off, 8);
        }
        if (hi && u < 4) {
            const float pk = (u == 0) ? p0 : (u == 1) ? p1 : (u == 2) ? p2 : p3;
            out[bb * 4 + u] = pk + b_fc[u];
        }
    }
}

extern "C" void kernel_launch(void* const* d_in, const int* in_sizes, int n_in,
                              void* d_out, int out_size)
{
    const float* x    = (const float*)d_in[0];
    const float* w_ih = (const float*)d_in[1];
    const float* w_hh = (const float*)d_in[2];
    const float* b_ih = (const float*)d_in[3];
    const float* b_hh = (const float*)d_in[4];
    const float* w_fc = (const float*)d_in[5];
    const float* b_fc = (const float*)d_in[6];
    float* out = (float*)d_out;

    // 4 batches per warp (2 groups x 2 interleaved chains) -> 1024 warps.
    const int threads = 32;
    const int blocks  = B_TOTAL / 4;
    lstm_fused_kernel<<<blocks, threads>>>(x, w_ih, w_hh, b_ih, b_hh, w_fc, b_fc, out);
}